// round 16
// baseline (speedup 1.0000x reference)
#include <cuda_runtime.h>
#include <cuda_bf16.h>
#include <cstdint>

#define HH 16
#define SS 2048
#define DD 128
#define BM 128
#define BN 64
#define NT 256
#define NELEM (2 * HH * SS * DD)

// ---- device scratch: split K and transposed-split V (bf16 hi/lo) ----
__device__ __nv_bfloat16 g_Khi[NELEM];
__device__ __nv_bfloat16 g_Klo[NELEM];
__device__ __nv_bfloat16 g_VThi[NELEM];   // [bh][d][s]
__device__ __nv_bfloat16 g_VTlo[NELEM];

// ---- main-kernel smem layout (bytes) ----
#define OFF_AMCX 0                     // 2 bufs x (am 256B + cx 256B); reused as zred[128] at epilogue
#define OFF_QHI  1024                  // 128 rows x 256B
#define OFF_QLO  33792
#define OFF_KV   66560                 // 2 bufs x 64KB; reused as O-reduction (128 x 132 fp32) at epilogue
#define SMEM_TOTAL 197632

__device__ __forceinline__ uint32_t smem_u32(const void* p){
    uint32_t a;
    asm("{ .reg .u64 t; cvta.to.shared.u64 t, %1; cvt.u32.u64 %0, t; }" : "=r"(a) : "l"(p));
    return a;
}
__device__ __forceinline__ void split2(float x, float y, uint32_t& hi, uint32_t& lo){
    __nv_bfloat162 h = __floats2bfloat162_rn(x, y);
    __nv_bfloat162 l = __floats2bfloat162_rn(x - __bfloat162float(h.x), y - __bfloat162float(h.y));
    hi = *reinterpret_cast<uint32_t*>(&h);
    lo = *reinterpret_cast<uint32_t*>(&l);
}
__device__ __forceinline__ void mma_bf16(float* d, const uint32_t* a, uint32_t b0, uint32_t b1){
    asm("mma.sync.aligned.m16n8k16.row.col.f32.bf16.bf16.f32 "
        "{%0,%1,%2,%3}, {%4,%5,%6,%7}, {%8,%9}, {%0,%1,%2,%3};"
        : "+f"(d[0]), "+f"(d[1]), "+f"(d[2]), "+f"(d[3])
        : "r"(a[0]), "r"(a[1]), "r"(a[2]), "r"(a[3]), "r"(b0), "r"(b1));
}
__device__ __forceinline__ void ldsm4(uint32_t* r, uint32_t addr){
    asm volatile("ldmatrix.sync.aligned.m8n8.x4.shared.b16 {%0,%1,%2,%3}, [%4];"
        : "=r"(r[0]), "=r"(r[1]), "=r"(r[2]), "=r"(r[3]) : "r"(addr));
}
__device__ __forceinline__ void cpa16(uint32_t dst, const void* src){
    asm volatile("cp.async.cg.shared.global [%0], [%1], 16;" :: "r"(dst), "l"(src));
}
__device__ __forceinline__ void cpa8(uint32_t dst, const void* src){
    asm volatile("cp.async.ca.shared.global [%0], [%1], 8;" :: "r"(dst), "l"(src));
}
#define CP_COMMIT() asm volatile("cp.async.commit_group;" ::: "memory")
#define CP_WAIT0()  asm volatile("cp.async.wait_group 0;" ::: "memory")
#define CP_WAIT1()  asm volatile("cp.async.wait_group 1;" ::: "memory")

// =================== prepass kernels ===================
__global__ void prep_k_kernel(const float* __restrict__ K){
    size_t i = (size_t)blockIdx.x * 256 + threadIdx.x;   // float4 index
    float4 v = ((const float4*)K)[i];
    uint32_t h0, l0, h1, l1;
    split2(v.x, v.y, h0, l0);
    split2(v.z, v.w, h1, l1);
    ((uint2*)g_Khi)[i] = make_uint2(h0, h1);
    ((uint2*)g_Klo)[i] = make_uint2(l0, l1);
}
__global__ void prep_v_kernel(const float* __restrict__ V){
    __shared__ float ts[32][33];
    const int bh = blockIdx.z, d0 = blockIdx.y * 32, s0 = blockIdx.x * 32;
    const int t = threadIdx.x, i = t >> 3, j4 = (t & 7) * 4;
    const float* Vp = V + ((size_t)bh * SS + s0) * DD + d0;
    float4 v = *(const float4*)(Vp + (size_t)i * DD + j4);
    ts[i][j4] = v.x; ts[i][j4 + 1] = v.y; ts[i][j4 + 2] = v.z; ts[i][j4 + 3] = v.w;
    __syncthreads();
    float a = ts[j4][i], b = ts[j4 + 1][i], c = ts[j4 + 2][i], d = ts[j4 + 3][i];
    uint32_t h0, l0, h1, l1;
    split2(a, b, h0, l0);
    split2(c, d, h1, l1);
    size_t dst = ((size_t)bh * DD + d0 + i) * SS + s0 + j4;
    *(uint2*)(g_VThi + dst) = make_uint2(h0, h1);
    *(uint2*)(g_VTlo + dst) = make_uint2(l0, l1);
}

// =================== main kernel helpers ===================
__device__ __forceinline__ void issue_loads(const __nv_bfloat16* Khb, const __nv_bfloat16* Klb,
                                            const __nv_bfloat16* Vhb, const __nv_bfloat16* Vlb,
                                            const float* AM, const float* CTX, size_t bS,
                                            int kbase, int buf, uint32_t sb, int tid)
{
    const uint32_t kv = sb + OFF_KV + (uint32_t)buf * 65536u;
    #pragma unroll
    for (int i = 0; i < 4; ++i){                      // K: 64 rows x 16 chunks
        int flat = tid + i * NT;
        int r = flat >> 4, c = flat & 15;
        uint32_t o = (uint32_t)r * 256u + ((((uint32_t)c) ^ ((uint32_t)r & 7u)) << 4);
        cpa16(kv + o,          (const char*)(Khb + (size_t)(kbase + r) * DD) + c * 16);
        cpa16(kv + 16384u + o, (const char*)(Klb + (size_t)(kbase + r) * DD) + c * 16);
    }
    #pragma unroll
    for (int i = 0; i < 4; ++i){                      // VT: 128 rows x 8 chunks
        int flat = tid + i * NT;
        int d = flat >> 3, c = flat & 7;
        uint32_t o = (uint32_t)d * 128u + ((((uint32_t)c) ^ ((uint32_t)d & 7u)) << 4);
        cpa16(kv + 32768u + o, (const char*)(Vhb + (size_t)d * SS + kbase) + c * 16);
        cpa16(kv + 49152u + o, (const char*)(Vlb + (size_t)d * SS + kbase) + c * 16);
    }
    if (tid < 32)       cpa8(sb + OFF_AMCX + buf * 512 + tid * 8,              AM  + bS + kbase + 2 * tid);
    else if (tid < 64)  cpa8(sb + OFF_AMCX + buf * 512 + 256 + (tid - 32) * 8, CTX + bS + kbase + 2 * (tid - 32));
    CP_COMMIT();
}

__global__ __launch_bounds__(NT, 1)
void attn_hmma_kernel(const float* __restrict__ Q,
                      const float* __restrict__ AM,
                      const float* __restrict__ HM,
                      const float* __restrict__ CTX,
                      float* __restrict__ out)
{
    extern __shared__ char sm[];
    const uint32_t sb = smem_u32(sm);
    const int tid = threadIdx.x, wid = tid >> 5, lane = tid & 31;

    const int it = (gridDim.x - 1) - blockIdx.x;   // heavy q-tiles first
    const int h = blockIdx.y, b = blockIdx.z;
    const int bh = b * HH + h;
    const int q0 = it * BM;
    const int nt = 2 * (it + 1);

    const float* Qp = Q + ((size_t)bh * SS + q0) * DD;
    const __nv_bfloat16* Khb = g_Khi  + (size_t)bh * SS * DD;
    const __nv_bfloat16* Klb = g_Klo  + (size_t)bh * SS * DD;
    const __nv_bfloat16* Vhb = g_VThi + (size_t)bh * SS * DD;
    const __nv_bfloat16* Vlb = g_VTlo + (size_t)bh * SS * DD;
    const size_t bS = (size_t)b * SS;

    // ---- prologue: start tile-0 streaming, overlap with Q load+split ----
    issue_loads(Khb, Klb, Vhb, Vlb, AM, CTX, bS, 0, 0, sb, tid);
    {
        const float4* Qg = (const float4*)Qp;
        #pragma unroll
        for (int i = 0; i < 16; ++i){
            int flat = tid + i * NT;
            int r = flat >> 5, g = flat & 31;
            float4 v = Qg[flat];
            uint32_t h0, l0, h1, l1;
            split2(v.x, v.y, h0, l0);
            split2(v.z, v.w, h1, l1);
            uint32_t o = (uint32_t)r * 256u
                       + ((((uint32_t)(g >> 1)) ^ ((uint32_t)r & 7u)) << 4)
                       + (((uint32_t)(g & 1)) << 3);
            *(uint2*)(sm + OFF_QHI + o) = make_uint2(h0, h1);
            *(uint2*)(sm + OFF_QLO + o) = make_uint2(l0, l1);
        }
    }

    // ---- 4x2 warp grid: rg = row group (32 rows), ch = key half (32 keys) ----
    const int rg = wid & 3, ch = wid >> 2;
    const uint32_t hi4 = lane >> 4;
    const int rB  = (lane & 7) + ((lane >> 4) & 1) * 8;
    const uint32_t cof = (lane >> 3) & 1;
    const int g    = lane >> 2;
    const int colt = 2 * (lane & 3);

    // A-frag rows for the two m16 blocks
    int rowAm[2];  uint32_t qh_ad[2], ql_ad[2], swAm[2];
    #pragma unroll
    for (int mb = 0; mb < 2; ++mb){
        rowAm[mb] = 32 * rg + 16 * mb + (lane & 15);
        qh_ad[mb] = sb + OFF_QHI + rowAm[mb] * 256;
        ql_ad[mb] = sb + OFF_QLO + rowAm[mb] * 256;
        swAm[mb]  = rowAm[mb] & 7;
    }
    const int qgr[2] = { q0 + 32 * rg + g, q0 + 32 * rg + 16 + g };  // rows for c0/c1 per mb (+8 for c2/c3)

    float oacc[32][4];                     // [mb*16 + nb][4] : 32 rows x 128 dims partial-O
    #pragma unroll
    for (int i = 0; i < 32; ++i)
        #pragma unroll
        for (int j = 0; j < 4; ++j) oacc[i][j] = 0.f;
    float zt0[2] = {0.f, 0.f}, zt1[2] = {0.f, 0.f};

    for (int jt = 0; jt < nt; ++jt){
        const int kbase = jt * BN;
        const int cur = jt & 1;
        const uint32_t kvb = sb + OFF_KV + (uint32_t)cur * 65536u;

        __syncthreads();      // all warps done reading buf cur^1 (tile jt-1)
        if (jt + 1 < nt){
            issue_loads(Khb, Klb, Vhb, Vlb, AM, CTX, bS, (jt + 1) * BN, cur ^ 1, sb, tid);
            CP_WAIT1();       // tile jt complete (jt+1 may stay in flight)
        } else {
            CP_WAIT0();
        }
        __syncthreads();      // tile jt visible to all threads

        // causal skip: whole 32x32 warp-block above the diagonal
        if (kbase + 32 * ch > q0 + 32 * rg + 31) continue;

        const float* amb = (const float*)(sm + OFF_AMCX + cur * 512);
        const float* cxb = amb + 64;

        // ==== S = Q K^T : 32 rows x 32 keys, 192 mma, 64 ldsm ====
        float sacc[2][4][4];
        #pragma unroll
        for (int mb = 0; mb < 2; ++mb)
            #pragma unroll
            for (int i = 0; i < 4; ++i)
                #pragma unroll
                for (int j = 0; j < 4; ++j) sacc[mb][i][j] = 0.f;

        #pragma unroll
        for (int kb = 0; kb < 8; ++kb){
            uint32_t ah[2][4], al[2][4];
            #pragma unroll
            for (int mb = 0; mb < 2; ++mb){
                uint32_t coff = (((uint32_t)(2 * kb) + hi4) ^ swAm[mb]) << 4;
                ldsm4(ah[mb], qh_ad[mb] + coff);
                ldsm4(al[mb], ql_ad[mb] + coff);
            }
            uint32_t bh4[2][4], bl4[2][4];
            #pragma unroll
            for (int nb = 0; nb < 2; ++nb){
                int rowB = 32 * ch + 16 * nb + rB;
                uint32_t ko = (uint32_t)rowB * 256u
                            + ((((uint32_t)(2 * kb) + cof) ^ ((uint32_t)rowB & 7u)) << 4);
                ldsm4(bh4[nb], kvb + ko);
                ldsm4(bl4[nb], kvb + 16384u + ko);
            }
            #pragma unroll
            for (int mb = 0; mb < 2; ++mb)
                #pragma unroll
                for (int nb = 0; nb < 2; ++nb){          // hi x hi
                    mma_bf16(sacc[mb][2 * nb],     ah[mb], bh4[nb][0], bh4[nb][1]);
                    mma_bf16(sacc[mb][2 * nb + 1], ah[mb], bh4[nb][2], bh4[nb][3]);
                }
            #pragma unroll
            for (int mb = 0; mb < 2; ++mb)
                #pragma unroll
                for (int nb = 0; nb < 2; ++nb){          // hi x lo
                    mma_bf16(sacc[mb][2 * nb],     ah[mb], bl4[nb][0], bl4[nb][1]);
                    mma_bf16(sacc[mb][2 * nb + 1], ah[mb], bl4[nb][2], bl4[nb][3]);
                }
            #pragma unroll
            for (int mb = 0; mb < 2; ++mb)
                #pragma unroll
                for (int nb = 0; nb < 2; ++nb){          // lo x hi
                    mma_bf16(sacc[mb][2 * nb],     al[mb], bh4[nb][0], bh4[nb][1]);
                    mma_bf16(sacc[mb][2 * nb + 1], al[mb], bh4[nb][2], bh4[nb][3]);
                }
        }

        // ==== softmax (m=0): 32x32 block; P -> bf16 hi/lo frags ====
        uint32_t PH[2][4][2], PL[2][4][2];
        #pragma unroll
        for (int mb = 0; mb < 2; ++mb){
            const int qg0 = qgr[mb], qg1 = qg0 + 8;
            #pragma unroll
            for (int j = 0; j < 4; ++j){
                int col = kbase + 32 * ch + 8 * j + colt;
                float2 am2 = *(const float2*)&amb[32 * ch + 8 * j + colt];
                float2 cx2 = *(const float2*)&cxb[32 * ch + 8 * j + colt];
                float p0 = (col     <= qg0) ? __expf(sacc[mb][j][0] + am2.x) : 0.f;
                float p1 = (col + 1 <= qg0) ? __expf(sacc[mb][j][1] + am2.y) : 0.f;
                float p2 = (col     <= qg1) ? __expf(sacc[mb][j][2] + am2.x) : 0.f;
                float p3 = (col + 1 <= qg1) ? __expf(sacc[mb][j][3] + am2.y) : 0.f;
                zt0[mb] += p0 + p1;  zt1[mb] += p2 + p3;   // Z uses UNSCALED p
                p0 *= cx2.x; p1 *= cx2.y;                  // ctx applied post-softmax
                p2 *= cx2.x; p3 *= cx2.y;
                split2(p0, p1, PH[mb][j][0], PL[mb][j][0]);
                split2(p2, p3, PH[mb][j][1], PL[mb][j][1]);
            }
        }

        // ==== O += P V : 32 keys x 128 dims, 192 mma, 32 ldsm ====
        #pragma unroll
        for (int j2 = 0; j2 < 2; ++j2){
            const int kv16 = 2 * ch + j2;            // k16 index within the 64-key tile
            uint32_t Ahf[2][4], Alf[2][4];
            #pragma unroll
            for (int mb = 0; mb < 2; ++mb){
                Ahf[mb][0] = PH[mb][2 * j2][0];  Ahf[mb][1] = PH[mb][2 * j2][1];
                Ahf[mb][2] = PH[mb][2 * j2 + 1][0]; Ahf[mb][3] = PH[mb][2 * j2 + 1][1];
                Alf[mb][0] = PL[mb][2 * j2][0];  Alf[mb][1] = PL[mb][2 * j2][1];
                Alf[mb][2] = PL[mb][2 * j2 + 1][0]; Alf[mb][3] = PL[mb][2 * j2 + 1][1];
            }
            #pragma unroll
            for (int nv = 0; nv < 8; ++nv){
                int rowV = 16 * nv + rB;
                uint32_t vo = (uint32_t)rowV * 128u
                            + ((((uint32_t)(2 * kv16) + cof) ^ ((uint32_t)rowV & 7u)) << 4);
                uint32_t vh[4], vl[4];
                ldsm4(vh, kvb + 32768u + vo);
                ldsm4(vl, kvb + 49152u + vo);
                #pragma unroll
                for (int mb = 0; mb < 2; ++mb){          // Ph x Vh
                    mma_bf16(oacc[mb * 16 + 2 * nv],     Ahf[mb], vh[0], vh[1]);
                    mma_bf16(oacc[mb * 16 + 2 * nv + 1], Ahf[mb], vh[2], vh[3]);
                }
                #pragma unroll
                for (int mb = 0; mb < 2; ++mb){          // Ph x Vl
                    mma_bf16(oacc[mb * 16 + 2 * nv],     Ahf[mb], vl[0], vl[1]);
                    mma_bf16(oacc[mb * 16 + 2 * nv + 1], Ahf[mb], vl[2], vl[3]);
                }
                #pragma unroll
                for (int mb = 0; mb < 2; ++mb){          // Pl x Vh
                    mma_bf16(oacc[mb * 16 + 2 * nv],     Alf[mb], vh[0], vh[1]);
                    mma_bf16(oacc[mb * 16 + 2 * nv + 1], Alf[mb], vh[2], vh[3]);
                }
            }
        }
    }

    // ==== epilogue: pair-reduce O and Z across key halves, scale, store ====
    __syncthreads();                                   // done with KV smem
    float* red  = (float*)(sm + OFF_KV);               // 128 rows x 132 fp32 (padded)
    float* zred = (float*)(sm + OFF_AMCX);             // zred[128]

    #pragma unroll
    for (int mb = 0; mb < 2; ++mb){                    // in-warp Z reduce over lane quads
        zt0[mb] += __shfl_xor_sync(0xffffffffu, zt0[mb], 1);
        zt0[mb] += __shfl_xor_sync(0xffffffffu, zt0[mb], 2);
        zt1[mb] += __shfl_xor_sync(0xffffffffu, zt1[mb], 1);
        zt1[mb] += __shfl_xor_sync(0xffffffffu, zt1[mb], 2);
    }

    if (ch == 1){                                      // upper key-half: publish partials
        #pragma unroll
        for (int mb = 0; mb < 2; ++mb){
            int r0 = 32 * rg + 16 * mb + g;
            #pragma unroll
            for (int nb = 0; nb < 16; ++nb){
                *(float2*)&red[(size_t)r0 * 132 + 8 * nb + colt]
                    = make_float2(oacc[mb * 16 + nb][0], oacc[mb * 16 + nb][1]);
                *(float2*)&red[(size_t)(r0 + 8) * 132 + 8 * nb + colt]
                    = make_float2(oacc[mb * 16 + nb][2], oacc[mb * 16 + nb][3]);
            }
            if ((lane & 3) == 0){
                zred[32 * rg + 16 * mb + g]     = zt0[mb];
                zred[32 * rg + 16 * mb + g + 8] = zt1[mb];
            }
        }
    }
    __syncthreads();
    if (ch == 0){                                      // lower key-half: combine + store
        const float hm = HM[h];
        #pragma unroll
        for (int mb = 0; mb < 2; ++mb){
            int r0 = 32 * rg + 16 * mb + g;
            float i0 = hm / (zt0[mb] + zred[r0]);
            float i1 = hm / (zt1[mb] + zred[r0 + 8]);
            float* O0 = out + ((size_t)bh * SS + q0 + r0) * DD;
            float* O1 = O0 + 8 * DD;
            #pragma unroll
            for (int nb = 0; nb < 16; ++nb){
                float2 a0 = *(const float2*)&red[(size_t)r0 * 132 + 8 * nb + colt];
                float2 a1 = *(const float2*)&red[(size_t)(r0 + 8) * 132 + 8 * nb + colt];
                *(float2*)&O0[8 * nb + colt] =
                    make_float2((oacc[mb * 16 + nb][0] + a0.x) * i0,
                                (oacc[mb * 16 + nb][1] + a0.y) * i0);
                *(float2*)&O1[8 * nb + colt] =
                    make_float2((oacc[mb * 16 + nb][2] + a1.x) * i1,
                                (oacc[mb * 16 + nb][3] + a1.y) * i1);
            }
        }
    }
}

extern "C" void kernel_launch(void* const* d_in, const int* in_sizes, int n_in,
                              void* d_out, int out_size)
{
    (void)in_sizes; (void)n_in; (void)out_size;
    const float* Q   = (const float*)d_in[0];
    const float* K   = (const float*)d_in[1];
    const float* V   = (const float*)d_in[2];
    const float* AM  = (const float*)d_in[3];
    const float* HM  = (const float*)d_in[4];
    const float* CTX = (const float*)d_in[5];
    float* out = (float*)d_out;

    cudaFuncSetAttribute(attn_hmma_kernel,
                         cudaFuncAttributeMaxDynamicSharedMemorySize, SMEM_TOTAL);

    prep_k_kernel<<<NELEM / 4 / 256, 256>>>(K);
    prep_v_kernel<<<dim3(SS / 32, DD / 32, 2 * HH), 256>>>(V);

    dim3 grid(SS / BM, HH, 2);
    attn_hmma_kernel<<<grid, NT, SMEM_TOTAL>>>(Q, AM, HM, CTX, out);
}